// round 14
// baseline (speedup 1.0000x reference)
#include <cuda_runtime.h>

#define B 8
#define C 512
#define HW 4096
#define TOTAL (B*C*HW)          // 16,777,216
#define TOTAL4 (TOTAL/4)        // 4,194,304
#define CG 128                  // chain grid: 128 CTAs x 256 thr = 1024 warps
#define CT 256
#define LGRID 1184              // fuse grid: 148 SMs x 8 CTAs

// Scratch (device globals — no allocation allowed)
__device__ float g_text_proj[B*C];
__device__ float g_v_rgb[B*C];
__device__ float g_v_dep[B*C];
__device__ float g_rd[B*2*C];     // per b: [r(512) | d(512)]
__device__ float g_fused[B*C];
__device__ double g_acc[2];       // zero-init; finalize resets after use (replay-safe)
__device__ unsigned int g_count;  // loss finalize counter

// Chain barrier: generation counter, monotonic across graph replays.
__device__ unsigned int g_bar_cnt;
__device__ volatile unsigned int g_bar_gen;

// wait=false: arrive-only (used by blocks that exit after this stage)
__device__ __forceinline__ void chain_bar(bool wait) {
    __syncthreads();
    if (threadIdx.x == 0) {
        __threadfence();
        unsigned gen = g_bar_gen;
        if (atomicAdd(&g_bar_cnt, 1u) == CG - 1u) {
            g_bar_cnt = 0;
            __threadfence();
            g_bar_gen = gen + 1u;
        } else if (wait) {
            while (g_bar_gen == gen) { }    // tight poll: ~L2 latency detection
        }
        __threadfence();
    }
    __syncthreads();
}

__device__ __forceinline__ void pf_l2(const float* p) {
    asm volatile("prefetch.global.L2 [%0];" :: "l"(p));
}

// Warp computes one output channel for all 8 batches; 128 float4 of X per batch in smem.
__device__ __forceinline__ void gemv_acc128(
    const float4* __restrict__ sx4, const float4* __restrict__ w4row,
    float* acc, int lane)
{
#pragma unroll
    for (int i = 0; i < 4; ++i) {
        float4 w = w4row[i * 32 + lane];
#pragma unroll
        for (int b = 0; b < B; ++b) {
            float4 x = sx4[b * 128 + i * 32 + lane];
            acc[b] += w.x * x.x + w.y * x.y + w.z * x.z + w.w * x.w;
        }
    }
}

// xor-reduce: afterwards EVERY lane holds the full sums for all 8 batches.
__device__ __forceinline__ void warp_allreduce(float* acc) {
#pragma unroll
    for (int b = 0; b < B; ++b) {
#pragma unroll
        for (int o = 16; o > 0; o >>= 1)
            acc[b] += __shfl_xor_sync(0xffffffffu, acc[b], o);
    }
}

// GEMV chain + BN/gate/fuse: 128 CTAs x 256 threads (1024 warp-channels).
__global__ void __launch_bounds__(CT) chain_kernel(
    const float* __restrict__ text,
    const float* __restrict__ tp_w,   const float* __restrict__ tp_b,
    const float* __restrict__ rgb_wv, const float* __restrict__ rgb_bv,
    const float* __restrict__ dep_wv, const float* __restrict__ dep_bv,
    const float* __restrict__ rgb_wo, const float* __restrict__ rgb_bo,
    const float* __restrict__ dep_wo, const float* __restrict__ dep_bo,
    const float* __restrict__ gate_w, const float* __restrict__ gate_b,
    const float* __restrict__ bn_g,   const float* __restrict__ bn_b)
{
#if __CUDA_ARCH__ >= 900
    cudaTriggerProgrammaticLaunchCompletion();   // all threads
#endif
    __shared__ float4 sx4[1024];   // 16KB staging
    int tid = threadIdx.x;
    int warp = tid >> 5, lane = tid & 31;
    int gwarp = blockIdx.x * 8 + warp;          // 0..1023
    bool lower = (gwarp < 512);                 // blocks 0..63

    // ---- L2 prefetch of this warp's stage-2/3/4 weight rows ----
    {
        const float* s2row = lower ? (rgb_wv + (size_t)gwarp * 512)
                                   : (dep_wv + (size_t)(gwarp - 512) * 512);
        if (lane < 16) pf_l2(s2row + lane * 32);
        const float* s3row = lower ? (rgb_wo + (size_t)gwarp * 512)
                                   : (dep_wo + (size_t)(gwarp - 512) * 512);
        if (lane < 16) pf_l2(s3row + lane * 32);
        if (lower) pf_l2(gate_w + (size_t)gwarp * 1024 + lane * 32);  // full 4KB row
    }

    // ---- S1: text_proj = text @ tp_w.T + tp_b (channels on blocks 0..63) ----
    if (lower) {
        const float4* X4 = reinterpret_cast<const float4*>(text);
        for (int i = tid; i < 1024; i += CT) sx4[i] = X4[i];
        __syncthreads();
        float acc[B] = {0,0,0,0,0,0,0,0};
        gemv_acc128(sx4, reinterpret_cast<const float4*>(tp_w) + (size_t)gwarp * 128, acc, lane);
        warp_allreduce(acc);
        if (lane == 0) {
            float bv = tp_b[gwarp];
#pragma unroll
            for (int b = 0; b < B; ++b) g_text_proj[b * C + gwarp] = acc[b] + bv;
        }
    }
    chain_bar(true);

    // ---- S2: v = text_proj @ Wv.T + bv ----
    {
        const float4* X4 = reinterpret_cast<const float4*>(g_text_proj);
        for (int i = tid; i < 1024; i += CT) sx4[i] = X4[i];
        __syncthreads();
        float acc[B] = {0,0,0,0,0,0,0,0};
        if (lower) {
            gemv_acc128(sx4, reinterpret_cast<const float4*>(rgb_wv) + (size_t)gwarp * 128, acc, lane);
            warp_allreduce(acc);
            if (lane == 0) {
                float bv = rgb_bv[gwarp];
#pragma unroll
                for (int b = 0; b < B; ++b) g_v_rgb[b * C + gwarp] = acc[b] + bv;
            }
        } else {
            int c = gwarp - 512;
            gemv_acc128(sx4, reinterpret_cast<const float4*>(dep_wv) + (size_t)c * 128, acc, lane);
            warp_allreduce(acc);
            if (lane == 0) {
                float bv = dep_bv[c];
#pragma unroll
                for (int b = 0; b < B; ++b) g_v_dep[b * C + c] = acc[b] + bv;
            }
        }
    }
    chain_bar(true);

    // ---- S3: r/d = v @ Wo.T + bo -> g_rd[b, r|d] ----
    {
        const float4* X4 = reinterpret_cast<const float4*>(lower ? g_v_rgb : g_v_dep);
        for (int i = tid; i < 1024; i += CT) sx4[i] = X4[i];
        __syncthreads();
        float acc[B] = {0,0,0,0,0,0,0,0};
        if (lower) {
            gemv_acc128(sx4, reinterpret_cast<const float4*>(rgb_wo) + (size_t)gwarp * 128, acc, lane);
            warp_allreduce(acc);
            if (lane == 0) {
                float bv = rgb_bo[gwarp];
#pragma unroll
                for (int b = 0; b < B; ++b) g_rd[b * 2 * C + gwarp] = acc[b] + bv;
            }
        } else {
            int c = gwarp - 512;
            gemv_acc128(sx4, reinterpret_cast<const float4*>(dep_wo) + (size_t)c * 128, acc, lane);
            warp_allreduce(acc);
            if (lane == 0) {
                float bv = dep_bo[c];
#pragma unroll
                for (int b = 0; b < B; ++b) g_rd[b * 2 * C + C + c] = acc[b] + bv;
            }
        }
    }
    // upper blocks arrive and exit; lower blocks wait then run S4+S5
    chain_bar(lower);
    if (!lower) return;

    // ---- S4 + S5 fused (blocks 0..63): gate GEMV (K=1024 in two 16KB passes)
    //      + BN over batch + sigmoid + fuse ----
    {
        const float4* rd4 = reinterpret_cast<const float4*>(g_rd);
        float acc[B] = {0,0,0,0,0,0,0,0};
#pragma unroll
        for (int p = 0; p < 2; ++p) {
            __syncthreads();
            for (int i = tid; i < 1024; i += CT)
                sx4[i] = rd4[(i >> 7) * 256 + p * 128 + (i & 127)];
            __syncthreads();
            gemv_acc128(sx4, reinterpret_cast<const float4*>(gate_w)
                             + (size_t)gwarp * 256 + p * 128, acc, lane);
        }
        warp_allreduce(acc);        // every lane now has all 8 batch sums

        int c = gwarp;
        float gbias = gate_b[c];
        float p[B];
        float mean = 0.f;
#pragma unroll
        for (int b = 0; b < B; ++b) { p[b] = acc[b] + gbias; mean += p[b]; }
        mean *= (1.f / B);
        float var = 0.f;
#pragma unroll
        for (int b = 0; b < B; ++b) { float d = p[b] - mean; var += d * d; }
        var *= (1.f / B);
        float rstd = rsqrtf(var + 1e-5f);
        float gg = bn_g[c], gb = bn_b[c];
        if (lane < B) {
            int b = lane;
            float xh   = (p[b] - mean) * rstd;
            float gate = 1.f / (1.f + expf(-(gg * xh + gb)));
            float r = g_rd[b * 2 * C + c];
            float d = g_rd[b * 2 * C + C + c];
            g_fused[b * C + c] = gate * r + (1.f - gate) * d;
        }
    }
}

// Secondary: interleaved read(128MB)+write(64MB) pass, 2-way unrolled for MLP.
__global__ void __launch_bounds__(256) fuse_loss_kernel(
    const float4* __restrict__ rgb, const float4* __restrict__ dep,
    float4* __restrict__ out, float* __restrict__ out_s)
{
#if __CUDA_ARCH__ >= 900
    cudaGridDependencySynchronize();   // chain complete + g_fused visible
#endif
    int tid = threadIdx.x;
    int stride = gridDim.x * blockDim.x;
    int t0 = blockIdx.x * blockDim.x + tid;
    float s2 = 0.f, s1 = 0.f;

    for (int i = t0; i < TOTAL4; i += 2 * stride) {
        int j = i + stride;
        float4 r0 = __ldcs(rgb + i);
        float4 d0 = __ldcs(dep + i);
        float f0 = g_fused[i >> 10];
        if (j < TOTAL4) {
            float4 r1 = __ldcs(rgb + j);
            float4 d1 = __ldcs(dep + j);
            float f1 = g_fused[j >> 10];
            float ex = r1.x - d1.x, ey = r1.y - d1.y, ez = r1.z - d1.z, ew = r1.w - d1.w;
            s2 += ex*ex + ey*ey + ez*ez + ew*ew;
            s1 += fabsf(ex) + fabsf(ey) + fabsf(ez) + fabsf(ew);
            __stcs(out + j, make_float4(f1, f1, f1, f1));
        }
        float dx = r0.x - d0.x, dy = r0.y - d0.y, dz = r0.z - d0.z, dw = r0.w - d0.w;
        s2 += dx*dx + dy*dy + dz*dz + dw*dw;
        s1 += fabsf(dx) + fabsf(dy) + fabsf(dz) + fabsf(dw);
        __stcs(out + i, make_float4(f0, f0, f0, f0));
    }

    // ---- Loss reduce + finalize ----
#pragma unroll
    for (int o = 16; o > 0; o >>= 1) {
        s2 += __shfl_down_sync(0xffffffffu, s2, o);
        s1 += __shfl_down_sync(0xffffffffu, s1, o);
    }
    __shared__ float sh2[8], sh1[8];
    int w = tid >> 5, l = tid & 31;
    if (l == 0) { sh2[w] = s2; sh1[w] = s1; }
    __syncthreads();
    if (tid == 0) {
        float t2 = 0.f, t1 = 0.f;
#pragma unroll
        for (int j = 0; j < 8; ++j) { t2 += sh2[j]; t1 += sh1[j]; }
        atomicAdd(&g_acc[0], (double)t2);
        atomicAdd(&g_acc[1], (double)t1);
        __threadfence();
        if (atomicAdd(&g_count, 1u) == gridDim.x - 1u) {
            g_count = 0;
            const double inv = 1.0 / (double)TOTAL;
            double a0 = atomicAdd(&g_acc[0], 0.0);
            double a1 = atomicAdd(&g_acc[1], 0.0);
            out_s[TOTAL]     = (float)(a0 * inv);   // pixel_loss
            out_s[TOTAL + 1] = (float)(a1 * inv);   // depth_loss
            g_acc[0] = 0.0; g_acc[1] = 0.0;          // reset for next replay
            __threadfence();
        }
    }
}

extern "C" void kernel_launch(void* const* d_in, const int* in_sizes, int n_in,
                              void* d_out, int out_size)
{
    const float* rgb      = (const float*)d_in[0];
    const float* dep      = (const float*)d_in[1];
    const float* text     = (const float*)d_in[2];
    const float* tp_w     = (const float*)d_in[3];
    const float* tp_b     = (const float*)d_in[4];
    const float* rgb_wqkv = (const float*)d_in[5];
    const float* rgb_bqkv = (const float*)d_in[6];
    const float* rgb_wo   = (const float*)d_in[7];
    const float* rgb_bo   = (const float*)d_in[8];
    const float* dep_wqkv = (const float*)d_in[9];
    const float* dep_bqkv = (const float*)d_in[10];
    const float* dep_wo   = (const float*)d_in[11];
    const float* dep_bo   = (const float*)d_in[12];
    const float* gate_w   = (const float*)d_in[13];
    const float* gate_b   = (const float*)d_in[14];
    const float* bn_g     = (const float*)d_in[15];
    const float* bn_b     = (const float*)d_in[16];
    float* out = (float*)d_out;

    chain_kernel<<<CG, CT>>>(
        text, tp_w, tp_b,
        rgb_wqkv + 2*C*C, rgb_bqkv + 2*C,
        dep_wqkv + 2*C*C, dep_bqkv + 2*C,
        rgb_wo, rgb_bo, dep_wo, dep_bo,
        gate_w, gate_b, bn_g, bn_b);

    cudaLaunchConfig_t cfg = {};
    cfg.gridDim  = dim3(LGRID);
    cfg.blockDim = dim3(256);
    cfg.dynamicSmemBytes = 0;
    cfg.stream = 0;
    cudaLaunchAttribute attr[1];
    attr[0].id = cudaLaunchAttributeProgrammaticStreamSerialization;
    attr[0].val.programmaticStreamSerializationAllowed = 1;
    cfg.attrs = attr;
    cfg.numAttrs = 1;
    cudaLaunchKernelEx(&cfg, fuse_loss_kernel,
                       (const float4*)rgb, (const float4*)dep, (float4*)out, out);
}